// round 8
// baseline (speedup 1.0000x reference)
#include <cuda_runtime.h>

#define NN (1 << 20)   // rows
#define DD 32          // dim
#define QQ 4           // stages
#define KK 256         // codewords per stage

static constexpr int THREADS = 256;
static constexpr int ROWS_PER_THREAD = 2;
static constexpr int ROWS_PER_BLOCK = THREADS * ROWS_PER_THREAD;  // 512
static constexpr int GRID = NN / ROWS_PER_BLOCK;                  // 2048

// Deterministic loss scratch (no atomics): one double per block.
__device__ double g_partials[GRID];

typedef unsigned long long u64;

__device__ __forceinline__ u64 fma2(u64 a, u64 b, u64 c) {
    u64 d;
    asm("fma.rn.f32x2 %0, %1, %2, %3;" : "=l"(d) : "l"(a), "l"(b), "l"(c));
    return d;
}
__device__ __forceinline__ u64 add2(u64 a, u64 b) {
    u64 d;
    asm("add.rn.f32x2 %0, %1, %2;" : "=l"(d) : "l"(a), "l"(b));
    return d;
}
__device__ __forceinline__ u64 mul2(u64 a, u64 b) {
    u64 d;
    asm("mul.rn.f32x2 %0, %1, %2;" : "=l"(d) : "l"(a), "l"(b));
    return d;
}
__device__ __forceinline__ float2 unpack2(u64 v) {
    float2 f;
    asm("mov.b64 {%0, %1}, %2;" : "=f"(f.x), "=f"(f.y) : "l"(v));
    return f;
}
__device__ __forceinline__ u64 pack2(float x, float y) {
    u64 v;
    asm("mov.b64 %0, {%1, %2};" : "=l"(v) : "f"(x), "f"(y));
    return v;
}
__device__ __forceinline__ u64 sub2(u64 a, u64 b) {
    float2 fa = unpack2(a), fb = unpack2(b);
    return pack2(__fsub_rn(fa.x, fb.x), __fsub_rn(fa.y, fb.y));
}

// DECISION ARITHMETIC (reference model): g = sequential ascending chain with
// SEPARATE mul and add (no FMA fusion), as emitted by XLA's dot/loop emitters
// without an LLVM contract flag. Full 256-codeword argmin, strict < (first min).
__device__ __noinline__ int sep_argmin(const u64* r, int lane, const u64* s_cb2,
                                       const float* s_ee, float rr)
{
    float rs[DD];
    #pragma unroll
    for (int j = 0; j < DD; j++) {
        float2 f = unpack2(r[j]);
        rs[j] = lane ? f.y : f.x;
    }
    float dmin = 3.4e38f;
    int best = 0;
    for (int k = 0; k < KK; k++) {
        const u64* cw = s_cb2 + (size_t)k * DD;
        float acc = 0.0f;
        #pragma unroll
        for (int j = 0; j < DD; j++)
            acc = __fadd_rn(acc, __fmul_rn(rs[j], unpack2(cw[j]).x));  // mul, then add
        float d = __fadd_rn(__fsub_rn(rr, __fmul_rn(2.0f, acc)), s_ee[k]);
        if (d < dmin) { dmin = d; best = k; }
    }
    return best;
}

__global__ __launch_bounds__(THREADS, 2)
void rvq_kernel(const float* __restrict__ x,
                const float* __restrict__ codebooks,
                float* __restrict__ out)
{
    extern __shared__ u64 smem_raw[];
    u64*  s_cb2 = smem_raw;                       // KK*DD u64: codeword value duplicated (e,e)
    float* s_ee = (float*)(smem_raw + KK * DD);   // KK floats: ||e_k||^2

    const int tid = threadIdx.x;
    const size_t row0 = (size_t)blockIdx.x * ROWS_PER_BLOCK + (size_t)tid * 2;

    // Residuals for 2 rows packed across f32x2 lanes: r[j] = (row0[j], row1[j]).
    u64 r[DD];
    {
        const float4* p0 = (const float4*)(x + row0 * DD);
        const float4* p1 = (const float4*)(x + (row0 + 1) * DD);
        #pragma unroll
        for (int j = 0; j < 8; j++) {
            float4 a = p0[j];
            float4 b = p1[j];
            r[4 * j + 0] = pack2(a.x, b.x);
            r[4 * j + 1] = pack2(a.y, b.y);
            r[4 * j + 2] = pack2(a.z, b.z);
            r[4 * j + 3] = pack2(a.w, b.w);
        }
    }

    float* oind = out + (size_t)NN * DD + 1;   // indices region (after x_q and loss)
    double loss_sum = 0.0;

    for (int q = 0; q < QQ; q++) {
        __syncthreads();  // previous stage done reading smem
        // ee_k: scalar sequential ascending, separate mul/add.
        {
            const float* src = codebooks + ((size_t)q * KK + tid) * DD;
            float acc = 0.0f;
            #pragma unroll
            for (int j = 0; j < DD; j++) {
                float e = src[j];
                s_cb2[tid * DD + j] = pack2(e, e);
                acc = __fadd_rn(acc, __fmul_rn(e, e));
            }
            s_ee[tid] = acc;
        }
        __syncthreads();

        // rr per row: sequential ascending, separate mul/add.
        float rr0, rr1;
        {
            u64 acc2 = 0ull;  // (0.f, 0.f)
            #pragma unroll
            for (int j = 0; j < DD; j++)
                acc2 = add2(acc2, mul2(r[j], r[j]));
            float2 f = unpack2(acc2);
            rr0 = f.x; rr1 = f.y;
        }

        // SCREENING pass (fast, fused FMA2 chains): argmin + second-min gap.
        // Fused-vs-separate divergence is bounded by ~3e-4 here; any row whose
        // top-2 gap exceeds SAFE_GAP has identical argmin under both schemes.
        const float SAFE_GAP = 1e-3f;
        float dmin0 = 3.4e38f, dmin1 = 3.4e38f;
        float dsec0 = 3.4e38f, dsec1 = 3.4e38f;
        int best0 = 0, best1 = 0;
        #pragma unroll 2
        for (int k = 0; k < KK; k++) {
            const ulonglong2* cw = (const ulonglong2*)(s_cb2 + k * DD);
            u64 acc = 0ull;  // (0.f, 0.f) -- sequential fused chain (screen only)
            #pragma unroll
            for (int jj = 0; jj < DD / 2; jj++) {
                ulonglong2 e2 = cw[jj];              // LDS.128, uniform addr (broadcast)
                acc = fma2(r[2 * jj],     e2.x, acc);
                acc = fma2(r[2 * jj + 1], e2.y, acc);
            }
            float2 g = unpack2(acc);
            float ee = s_ee[k];
            float d0 = __fadd_rn(__fsub_rn(rr0, __fmul_rn(2.0f, g.x)), ee);
            float d1 = __fadd_rn(__fsub_rn(rr1, __fmul_rn(2.0f, g.y)), ee);
            if (d0 < dmin0) { dsec0 = dmin0; dmin0 = d0; best0 = k; }
            else if (d0 < dsec0) { dsec0 = d0; }
            if (d1 < dmin1) { dsec1 = dmin1; dmin1 = d1; best1 = k; }
            else if (d1 < dsec1) { dsec1 = d1; }
        }

        // Contested rows (tiny fraction): exact separate-op re-decision.
        if (dsec0 - dmin0 < SAFE_GAP) best0 = sep_argmin(r, 0, s_cb2, s_ee, rr0);
        if (dsec1 - dmin1 < SAFE_GAP) best1 = sep_argmin(r, 1, s_cb2, s_ee, rr1);

        // Emit indices (as float) for this stage.
        oind[row0 * QQ + q]       = (float)best0;
        oind[(row0 + 1) * QQ + q] = (float)best1;

        // Residual update + loss, reference rounding sequence:
        //   t = xq - r;  xres = r + t;  r = r - xres;  loss += t*t
        const u64* e0 = s_cb2 + best0 * DD;
        const u64* e1 = s_cb2 + best1 * DD;
        u64 lacc = 0ull;
        #pragma unroll
        for (int j = 0; j < DD; j++) {
            float xq0 = unpack2(e0[j]).x;
            float xq1 = unpack2(e1[j]).x;
            u64 xq2 = pack2(xq0, xq1);
            u64 t2 = sub2(xq2, r[j]);
            lacc = fma2(t2, t2, lacc);
            u64 xres2 = add2(r[j], t2);
            r[j] = sub2(r[j], xres2);
        }
        float2 lf = unpack2(lacc);
        loss_sum += (double)lf.x + (double)lf.y;
    }

    // x_q = x - r_final (sub-ulp from the reference's running sum).
    {
        const float4* p0 = (const float4*)(x + row0 * DD);
        const float4* p1 = (const float4*)(x + (row0 + 1) * DD);
        float4* o0 = (float4*)(out + row0 * DD);
        float4* o1 = (float4*)(out + (row0 + 1) * DD);
        #pragma unroll
        for (int j = 0; j < 8; j++) {
            float4 a = p0[j];
            float4 b = p1[j];
            float2 r0 = unpack2(r[4 * j + 0]);
            float2 r1 = unpack2(r[4 * j + 1]);
            float2 r2 = unpack2(r[4 * j + 2]);
            float2 r3 = unpack2(r[4 * j + 3]);
            float4 w, z;
            w.x = __fsub_rn(a.x, r0.x); z.x = __fsub_rn(b.x, r0.y);
            w.y = __fsub_rn(a.y, r1.x); z.y = __fsub_rn(b.y, r1.y);
            w.z = __fsub_rn(a.z, r2.x); z.z = __fsub_rn(b.z, r2.y);
            w.w = __fsub_rn(a.w, r3.x); z.w = __fsub_rn(b.w, r3.y);
            o0[j] = w;
            o1[j] = z;
        }
    }

    // Deterministic per-block loss partial.
    double s = loss_sum;
    #pragma unroll
    for (int off = 16; off > 0; off >>= 1)
        s += __shfl_down_sync(0xffffffffu, s, off);
    __shared__ double wsum[THREADS / 32];
    if ((tid & 31) == 0) wsum[tid >> 5] = s;
    __syncthreads();
    if (tid == 0) {
        double b = 0.0;
        #pragma unroll
        for (int w = 0; w < THREADS / 32; w++) b += wsum[w];
        g_partials[blockIdx.x] = b;
    }
}

__global__ void rvq_finalize(float* __restrict__ out)
{
    __shared__ double sh[256];
    double s = 0.0;
    for (int i = threadIdx.x; i < GRID; i += 256) s += g_partials[i];  // fixed order
    sh[threadIdx.x] = s;
    __syncthreads();
    for (int stride = 128; stride > 0; stride >>= 1) {
        if (threadIdx.x < stride) sh[threadIdx.x] += sh[threadIdx.x + stride];
        __syncthreads();
    }
    if (threadIdx.x == 0) {
        // mean over Q of (codebook_loss + 0.25*commit_loss) = 1.25 * sum / (Q*N*D)
        out[(size_t)NN * DD] = (float)(sh[0] * 1.25 / ((double)QQ * NN * DD));
    }
}

extern "C" void kernel_launch(void* const* d_in, const int* in_sizes, int n_in,
                              void* d_out, int out_size)
{
    const float* x  = (const float*)d_in[0];
    const float* cb = (const float*)d_in[1];
    float* out = (float*)d_out;
    size_t smem = (size_t)KK * DD * sizeof(u64) + (size_t)KK * sizeof(float);  // 66560 B
    cudaFuncSetAttribute(rvq_kernel, cudaFuncAttributeMaxDynamicSharedMemorySize, (int)smem);
    rvq_kernel<<<GRID, THREADS, smem>>>(x, cb, out);
    rvq_finalize<<<1, 256>>>(out);
}